// round 1
// baseline (speedup 1.0000x reference)
#include <cuda_runtime.h>
#include <cuda_bf16.h>

// SimpleLSS: softmax-sum over depth bins == 1 (to fp32 rounding), so
// weighted == img_feat. The entire op is a bilinear upsample
// (24,256,16,44) -> (24,256,128,128), half-pixel centers, clamped edges.
// depth_logits is never read.

#define IN_H 16
#define IN_W 44
#define OUT_HW 128
#define PLANE_IN (IN_H * IN_W)     // 704
#define PLANE_OUT (OUT_HW * OUT_HW) // 16384

__global__ __launch_bounds__(256) void lss_resize_kernel(
    const float* __restrict__ img, float* __restrict__ out)
{
    const int plane = blockIdx.x;                 // (n*256 + c)
    const float* __restrict__ src = img + (long long)plane * PLANE_IN;
    float* __restrict__ dst = out + (long long)plane * PLANE_OUT;

    __shared__ float tile[PLANE_IN];

    // cooperative tile load (704 floats)
    for (int i = threadIdx.x; i < PLANE_IN; i += 256)
        tile[i] = src[i];
    __syncthreads();

    // 16384 outputs / (256 threads * 4 per thread) = 16 iterations
    #pragma unroll
    for (int it = 0; it < 16; ++it) {
        const int l = it * 1024 + threadIdx.x * 4; // linear out index, x%4==0
        const int y = l >> 7;
        const int x = l & 127;

        // vertical mapping: scale = 16/128 = 0.125
        float sy = fmaxf(((float)y + 0.5f) * 0.125f - 0.5f, 0.0f);
        int   y0 = (int)sy;
        float fy = sy - (float)y0;
        int   y1 = min(y0 + 1, IN_H - 1);
        const float* __restrict__ r0 = tile + y0 * IN_W;
        const float* __restrict__ r1 = tile + y1 * IN_W;

        float4 v;
        float* vp = reinterpret_cast<float*>(&v);
        #pragma unroll
        for (int j = 0; j < 4; ++j) {
            // horizontal mapping: scale = 44/128 = 0.34375 (exact in fp32)
            float sx = fmaxf(((float)(x + j) + 0.5f) * 0.34375f - 0.5f, 0.0f);
            int   x0 = (int)sx;
            float fx = sx - (float)x0;
            int   x1 = min(x0 + 1, IN_W - 1);
            float a = r0[x0] + fx * (r0[x1] - r0[x0]);
            float b = r1[x0] + fx * (r1[x1] - r1[x0]);
            vp[j] = a + fy * (b - a);
        }
        *reinterpret_cast<float4*>(dst + l) = v;
    }
}

extern "C" void kernel_launch(void* const* d_in, const int* in_sizes, int n_in,
                              void* d_out, int out_size)
{
    const float* img = (const float*)d_in[0];   // (24,256,16,44)
    float* out = (float*)d_out;                 // (24,256,128,128)
    const int planes = in_sizes[0] / PLANE_IN;  // 24*256 = 6144
    lss_resize_kernel<<<planes, 256>>>(img, out);
}

// round 2
// speedup vs baseline: 1.7424x; 1.7424x over previous
#include <cuda_runtime.h>
#include <cuda_bf16.h>

// SimpleLSS: softmax over depth sums to 1 -> weighted == img_feat.
// Whole op == bilinear upsample (24,256,16,44) -> (24,256,128,128),
// half-pixel centers, clamped edges. depth_logits never read.
//
// R2: separable two-pass interp. Horizontal pass once per input row into
// smem (scalar LDS, 4096/CTA), vertical pass reads contiguous rows with
// LDS.128 (8192/CTA) -> ~5x fewer L1tex wavefronts than R1's 65536 scalar LDS.

#define IN_H 16
#define IN_W 44
#define OUT_HW 128
#define PLANE_IN (IN_H * IN_W)      // 704
#define PLANE_OUT (OUT_HW * OUT_HW) // 16384

__global__ __launch_bounds__(256) void lss_resize_kernel(
    const float* __restrict__ img, float* __restrict__ out)
{
    const int plane = blockIdx.x;                 // n*256 + c
    const float* __restrict__ src = img + (long long)plane * PLANE_IN;
    float* __restrict__ dst = out + (long long)plane * PLANE_OUT;

    __shared__ float tile[PLANE_IN];          // raw 16x44 input
    __shared__ float hrow[IN_H * OUT_HW];     // 16x128 horizontally-interp'd

    // ---- load input plane (704 floats) ----
    for (int i = threadIdx.x; i < PLANE_IN; i += 256)
        tile[i] = src[i];
    __syncthreads();

    // ---- stage 1: horizontal interp, 16*128 = 2048 values, 8/thread ----
    #pragma unroll
    for (int k = 0; k < 8; ++k) {
        const int i = k * 256 + threadIdx.x;
        const int r = i >> 7;            // input row 0..15
        const int x = i & 127;           // output col 0..127
        // horizontal scale 44/128 = 0.34375 (exact fp32)
        float sx = fmaxf(((float)x + 0.5f) * 0.34375f - 0.5f, 0.0f);
        int   x0 = (int)sx;
        float fx = sx - (float)x0;
        int   x1 = min(x0 + 1, IN_W - 1);
        const float* rp = tile + r * IN_W;
        float v0 = rp[x0];
        hrow[i] = v0 + fx * (rp[x1] - v0);
    }
    __syncthreads();

    // ---- stage 2: vertical blend, 16384 outputs, float4 per iter ----
    #pragma unroll
    for (int it = 0; it < 16; ++it) {
        const int l = it * 1024 + threadIdx.x * 4;  // output linear idx
        const int y = l >> 7;                       // = it*8 + warp_id
        const int x = l & 127;

        // vertical scale 16/128 = 0.125
        float sy = fmaxf(((float)y + 0.5f) * 0.125f - 0.5f, 0.0f);
        int   y0 = (int)sy;
        float fy = sy - (float)y0;
        int   y1 = min(y0 + 1, IN_H - 1);

        float4 a = *reinterpret_cast<const float4*>(hrow + y0 * OUT_HW + x);
        float4 b = *reinterpret_cast<const float4*>(hrow + y1 * OUT_HW + x);
        float4 v;
        v.x = a.x + fy * (b.x - a.x);
        v.y = a.y + fy * (b.y - a.y);
        v.z = a.z + fy * (b.z - a.z);
        v.w = a.w + fy * (b.w - a.w);
        // streaming store: output is write-once, never re-read
        __stcs(reinterpret_cast<float4*>(dst + l), v);
    }
}

extern "C" void kernel_launch(void* const* d_in, const int* in_sizes, int n_in,
                              void* d_out, int out_size)
{
    const float* img = (const float*)d_in[0];   // (24,256,16,44)
    float* out = (float*)d_out;                 // (24,256,128,128)
    const int planes = in_sizes[0] / PLANE_IN;  // 6144
    lss_resize_kernel<<<planes, 256>>>(img, out);
}

// round 3
// speedup vs baseline: 1.7499x; 1.0043x over previous
#include <cuda_runtime.h>
#include <cuda_bf16.h>

// SimpleLSS: softmax over depth sums to 1 -> weighted == img_feat.
// Whole op == bilinear upsample (24,256,16,44) -> (24,256,128,128),
// half-pixel centers, clamped edges. depth_logits never read.
//
// R3: register-blocked vertical pass. Rows 8g+4..8g+11 share hrow pair
// (g, g+1), so load the pair once into registers and emit 8 rows.
// Stage-2 LDS.128 drops 8192 -> 1024 per CTA, freeing L1tex for stores.

#define IN_H 16
#define IN_W 44
#define OUT_HW 128
#define PLANE_IN (IN_H * IN_W)      // 704
#define PLANE_OUT (OUT_HW * OUT_HW) // 16384

__global__ __launch_bounds__(256) void lss_resize_kernel(
    const float* __restrict__ img, float* __restrict__ out)
{
    const int plane = blockIdx.x;                 // n*256 + c
    const float* __restrict__ src = img + (long long)plane * PLANE_IN;
    float* __restrict__ dst = out + (long long)plane * PLANE_OUT;

    __shared__ float tile[PLANE_IN];          // raw 16x44 input
    __shared__ float4 hrow[IN_H * 32];        // 16 rows x 128 floats (as float4)

    // ---- load input plane (704 floats) ----
    for (int i = threadIdx.x; i < PLANE_IN; i += 256)
        tile[i] = src[i];
    __syncthreads();

    // ---- stage 1: horizontal interp, 16*128 = 2048 values, 8/thread ----
    float* hrow_s = reinterpret_cast<float*>(hrow);
    #pragma unroll
    for (int k = 0; k < 8; ++k) {
        const int i = k * 256 + threadIdx.x;
        const int r = i >> 7;            // input row 0..15
        const int x = i & 127;           // output col 0..127
        // horizontal scale 44/128 = 0.34375 (exact fp32)
        float sx = fmaxf(((float)x + 0.5f) * 0.34375f - 0.5f, 0.0f);
        int   x0 = (int)sx;
        float fx = sx - (float)x0;
        int   x1 = min(x0 + 1, IN_W - 1);
        const float* rp = tile + r * IN_W;
        float v0 = rp[x0];
        hrow_s[i] = v0 + fx * (rp[x1] - v0);
    }
    __syncthreads();

    // ---- stage 2: vertical blend from registers ----
    // Warp layout: lane c owns x-chunk [4c, 4c+3]; each warp handles row
    // groups g = warp and g = warp+8. Group g covers output rows
    // 8g+4 .. 8g+11 (fy = 0.0625 + 0.125*r); group 0 also emits rows 0-3
    // (fy = 0, pure hrow[0]); group 15's b clamps to hrow[15] (delta = 0),
    // rows >= 128 are skipped.
    const int c = threadIdx.x & 31;      // x-chunk index
    const int w = threadIdx.x >> 5;      // warp id 0..7
    const int x = c * 4;

    #pragma unroll
    for (int s = 0; s < 2; ++s) {
        const int g = w + 8 * s;                         // 0..15
        float4 a = hrow[g * 32 + c];
        float4 b = hrow[min(g + 1, IN_H - 1) * 32 + c];
        float4 d;
        d.x = b.x - a.x; d.y = b.y - a.y;
        d.z = b.z - a.z; d.w = b.w - a.w;

        if (g == 0) {
            #pragma unroll
            for (int r = 0; r < 4; ++r)
                __stcs(reinterpret_cast<float4*>(dst + r * OUT_HW + x), a);
        }

        #pragma unroll
        for (int r = 0; r < 8; ++r) {
            const int y = 8 * g + 4 + r;
            if (y < OUT_HW) {
                const float fy = 0.0625f + 0.125f * (float)r;
                float4 v;
                v.x = a.x + fy * d.x;
                v.y = a.y + fy * d.y;
                v.z = a.z + fy * d.z;
                v.w = a.w + fy * d.w;
                __stcs(reinterpret_cast<float4*>(dst + y * OUT_HW + x), v);
            }
        }
    }
}

extern "C" void kernel_launch(void* const* d_in, const int* in_sizes, int n_in,
                              void* d_out, int out_size)
{
    const float* img = (const float*)d_in[0];   // (24,256,16,44)
    float* out = (float*)d_out;                 // (24,256,128,128)
    const int planes = in_sizes[0] / PLANE_IN;  // 6144
    lss_resize_kernel<<<planes, 256>>>(img, out);
}